// round 15
// baseline (speedup 1.0000x reference)
#include <cuda_runtime.h>

#define NN      256     // neurons (post)
#define NI      128     // sensory inputs
#define BATCH   1024
#define UNFOLDS 6
#define NB      7       // batch rows per CTA (147 CTAs * 7 = 1029 >= 1024)
#define NBP     8       // padded row length (2 x float4)
#define GRID    147
#define NT      768     // 3 groups of 256; group g reduces ~1/3 of the pre range

// Packed weights: (a = sigma/2, c = -sigma*mu/2, P = W*erev/2, Q = W/2)
// sigmoid(sigma*(v-mu)) = 0.5 + 0.5*tanh( (sigma/2)*v - (sigma*mu/2) )
// Constant halves of W*sig*erev / W*sig folded into g_knum/g_kden per n.
__device__ float4 g_rec[NN * NN];   // recurrent, [pre j][post n]
__device__ float4 g_sen[NI * NN];   // sensory,   [pre i][post n]
__device__ float  g_knum[NN];       // gleak*vleak + sum over pre of P
__device__ float  g_kden[NN];       // cm + gleak + sum over pre of Q

__device__ __forceinline__ float tanh_fast(float x) {
    float y;
    asm("tanh.approx.f32 %0, %1;" : "=f"(y) : "f"(x));
    return y;
}

// ---------------------------------------------------------------------------
// Prep kernels
// ---------------------------------------------------------------------------
__global__ void pack_rec_kernel(const float* __restrict__ mu,
                                const float* __restrict__ sigma,
                                const float* __restrict__ W,
                                const float* __restrict__ erev) {
    int idx = blockIdx.x * NN + threadIdx.x;   // j * NN + n
    float a = 0.5f * sigma[idx];
    float m = mu[idx];
    float q = 0.5f * W[idx];
    float e = erev[idx];
    g_rec[idx] = make_float4(a, -a * m, q * e, q);
}

__global__ void pack_sen_kernel(const float* __restrict__ smu,
                                const float* __restrict__ ssigma,
                                const float* __restrict__ sW,
                                const float* __restrict__ serev) {
    int idx = blockIdx.x * NN + threadIdx.x;   // i * NN + n
    float a = 0.5f * ssigma[idx];
    float m = smu[idx];
    float q = 0.5f * sW[idx];
    float e = serev[idx];
    g_sen[idx] = make_float4(a, -a * m, q * e, q);
}

__global__ void reduce_k_kernel(const float* __restrict__ W,
                                const float* __restrict__ erev,
                                const float* __restrict__ sW,
                                const float* __restrict__ serev,
                                const float* __restrict__ vleak,
                                const float* __restrict__ gleak,
                                const float* __restrict__ cm_t) {
    __shared__ float rp[128];
    __shared__ float rq[128];
    int n = blockIdx.x;
    int t = threadIdx.x;
    float sp = 0.0f, sq = 0.0f;
    for (int j = t; j < NN; j += 128) {
        float q = 0.5f * W[j * NN + n];
        sp += q * erev[j * NN + n];
        sq += q;
    }
    for (int i = t; i < NI; i += 128) {
        float q = 0.5f * sW[i * NN + n];
        sp += q * serev[i * NN + n];
        sq += q;
    }
    rp[t] = sp; rq[t] = sq;
    __syncthreads();
    for (int s = 64; s > 0; s >>= 1) {
        if (t < s) { rp[t] += rp[t + s]; rq[t] += rq[t + s]; }
        __syncthreads();
    }
    if (t == 0) {
        g_knum[n] = fmaf(gleak[n], vleak[n], rp[0]);
        g_kden[n] = cm_t[n] + gleak[n] + rq[0];
    }
}

// ---------------------------------------------------------------------------
// Main: 1 CTA/SM (GRID=147), 768 threads = 3 groups x 256. Thread owns output
// neuron n = tid&255; group g = tid>>8 reduces ~1/3 of the presynaptic range
// (j split 88/84/84). State/input stored TRANSPOSED + padded (sv[j][0..7]) so
// each j-body loads all 7 rows with 2 LDS.128 broadcasts instead of 7 LDS.
// Groups 1,2 write fp32 partials to smem; group 0 combines/divides. All fp32.
// ---------------------------------------------------------------------------
__global__ __launch_bounds__(NT, 1) void liquid_main_kernel(
    const float* __restrict__ inputs,
    const float* __restrict__ state,
    const float* __restrict__ map_w,
    const float* __restrict__ map_b,
    const float* __restrict__ cm_t,
    float* __restrict__ out,
    int copies) {

    __shared__ alignas(16) float sx[NI][NBP];  // mapped inputs, transposed
    __shared__ alignas(16) float sv[NN][NBP];  // v state, transposed
    __shared__ float pn1[NB][NN], pd1[NB][NN]; // group-1 partials
    __shared__ float pn2[NB][NN], pd2[NB][NN]; // group-2 partials

    const int tid = threadIdx.x;
    const int n   = tid & (NN - 1);
    const int g   = tid >> 8;        // 0, 1 or 2
    const int r0  = blockIdx.x * NB;

    // j-range per group (multiples of 4): 0..88, 88..172, 172..256
    const int jbs = (g == 0) ? 0 : (g == 1) ? 88 : 172;
    const int jes = (g == 0) ? 88 : (g == 1) ? 172 : 256;
    // i-range per group: 0..44, 44..88, 88..128
    const int ibs = (g == 0) ? 0 : (g == 1) ? 44 : 88;
    const int ies = (g == 0) ? 44 : (g == 1) ? 88 : 128;

    // Load + map inputs (x = inputs*map_w + map_b), transposed
    for (int idx = tid; idx < NB * NI; idx += NT) {
        int bb  = idx >> 7;
        int i   = idx & (NI - 1);
        int row = r0 + bb; if (row > BATCH - 1) row = BATCH - 1;
        sx[i][bb] = fmaf(inputs[row * NI + i], map_w[i], map_b[i]);
    }
    // Load v state, transposed
    for (int idx = tid; idx < NB * NN; idx += NT) {
        int bb  = idx >> 8;
        int j   = idx & (NN - 1);
        int row = r0 + bb; if (row > BATCH - 1) row = BATCH - 1;
        sv[j][bb] = state[row * NN + j];
    }
    __syncthreads();

    // ---- Sensory pass: group g reduces i in [ibs, ies) ----
    float snum[NB], sden[NB];
    #pragma unroll
    for (int bb = 0; bb < NB; bb++) { snum[bb] = 0.0f; sden[bb] = 0.0f; }

    #pragma unroll 4
    for (int i = ibs; i < ies; i++) {
        float4 w  = g_sen[i * NN + n];
        float4 xa = *reinterpret_cast<const float4*>(&sx[i][0]);
        float4 xb = *reinterpret_cast<const float4*>(&sx[i][4]);
        float xs[NB] = {xa.x, xa.y, xa.z, xa.w, xb.x, xb.y, xb.z};
        #pragma unroll
        for (int bb = 0; bb < NB; bb++) {
            float z = fmaf(w.x, xs[bb], w.y);
            float t = tanh_fast(z);
            snum[bb] = fmaf(w.z, t, snum[bb]);
            sden[bb] = fmaf(w.w, t, sden[bb]);
        }
    }
    if (g == 1) {
        #pragma unroll
        for (int bb = 0; bb < NB; bb++) { pn1[bb][n] = snum[bb]; pd1[bb][n] = sden[bb]; }
    } else if (g == 2) {
        #pragma unroll
        for (int bb = 0; bb < NB; bb++) { pn2[bb][n] = snum[bb]; pd2[bb][n] = sden[bb]; }
    }
    __syncthreads();

    const float cm = cm_t[n];
    if (g == 0) {
        const float kn = g_knum[n];
        const float kd = g_kden[n];
        #pragma unroll
        for (int bb = 0; bb < NB; bb++) {
            snum[bb] += pn1[bb][n] + pn2[bb][n] + kn;
            sden[bb] += pd1[bb][n] + pd2[bb][n] + kd;
        }
    }
    __syncthreads();   // partial buffers free for reuse in the step loop

    // ---- Unfold loop ----
    for (int step = 0; step < UNFOLDS; step++) {
        float num[NB], den[NB];
        if (g == 0) {
            #pragma unroll
            for (int bb = 0; bb < NB; bb++) {
                num[bb] = fmaf(cm, sv[n][bb], snum[bb]);
                den[bb] = sden[bb];
            }
        } else {
            #pragma unroll
            for (int bb = 0; bb < NB; bb++) { num[bb] = 0.0f; den[bb] = 0.0f; }
        }

        #pragma unroll 4
        for (int j = jbs; j < jes; j++) {
            float4 w  = g_rec[j * NN + n];
            float4 va = *reinterpret_cast<const float4*>(&sv[j][0]);
            float4 vb = *reinterpret_cast<const float4*>(&sv[j][4]);
            float vs[NB] = {va.x, va.y, va.z, va.w, vb.x, vb.y, vb.z};
            #pragma unroll
            for (int bb = 0; bb < NB; bb++) {
                float z = fmaf(w.x, vs[bb], w.y);
                float t = tanh_fast(z);
                num[bb] = fmaf(w.z, t, num[bb]);
                den[bb] = fmaf(w.w, t, den[bb]);
            }
        }

        if (g == 1) {
            #pragma unroll
            for (int bb = 0; bb < NB; bb++) { pn1[bb][n] = num[bb]; pd1[bb][n] = den[bb]; }
        } else if (g == 2) {
            #pragma unroll
            for (int bb = 0; bb < NB; bb++) { pn2[bb][n] = num[bb]; pd2[bb][n] = den[bb]; }
        }
        __syncthreads();   // partials visible; all sv reads complete
        if (g == 0) {
            float vf[NB];
            #pragma unroll
            for (int bb = 0; bb < NB; bb++) {
                float nu = num[bb] + pn1[bb][n] + pn2[bb][n];
                float de = den[bb] + pd1[bb][n] + pd2[bb][n];
                vf[bb] = __fdividef(nu, de);
            }
            *reinterpret_cast<float4*>(&sv[n][0]) =
                make_float4(vf[0], vf[1], vf[2], vf[3]);
            *reinterpret_cast<float4*>(&sv[n][4]) =
                make_float4(vf[4], vf[5], vf[6], vf[6]);
        }
        __syncthreads();
    }

    // ---- Output (reference returns (v, v) -> possibly 2 copies) ----
    // Group g writes copy g when copies > 1; otherwise group 0 writes.
    #pragma unroll
    for (int bb = 0; bb < NB; bb++) {
        int row = r0 + bb;
        if (row >= BATCH) continue;
        float v = sv[n][bb];
        if (copies > 1) {
            if (g < copies) out[g * (BATCH * NN) + row * NN + n] = v;
        } else if (g == 0) {
            out[row * NN + n] = v;
        }
    }
}

// ---------------------------------------------------------------------------
extern "C" void kernel_launch(void* const* d_in, const int* in_sizes, int n_in,
                              void* d_out, int out_size) {
    const float* inputs = (const float*)d_in[0];
    const float* state  = (const float*)d_in[1];
    const float* map_w  = (const float*)d_in[2];
    const float* map_b  = (const float*)d_in[3];
    const float* smu    = (const float*)d_in[4];
    const float* ssig   = (const float*)d_in[5];
    const float* sW     = (const float*)d_in[6];
    const float* serev  = (const float*)d_in[7];
    const float* mu     = (const float*)d_in[8];
    const float* sigma  = (const float*)d_in[9];
    const float* W      = (const float*)d_in[10];
    const float* erev   = (const float*)d_in[11];
    const float* vleak  = (const float*)d_in[12];
    const float* gleak  = (const float*)d_in[13];
    const float* cm     = (const float*)d_in[14];

    int copies = out_size / (BATCH * NN);
    if (copies < 1) copies = 1;

    pack_rec_kernel<<<NN, NN>>>(mu, sigma, W, erev);
    pack_sen_kernel<<<NI, NN>>>(smu, ssig, sW, serev);
    reduce_k_kernel<<<NN, 128>>>(W, erev, sW, serev, vleak, gleak, cm);
    liquid_main_kernel<<<GRID, NT>>>(inputs, state, map_w, map_b, cm,
                                     (float*)d_out, copies);
}